// round 13
// baseline (speedup 1.0000x reference)
#include <cuda_runtime.h>
#include <cuda_bf16.h>
#include <math.h>

// Oscillator: XLA rw16 cumsum association + div.full.f32 scale chain (bit-exact
// through x); sin via mod-2pi reduction + single MUFU.SIN. Persistent kernel,
// prep (64 blocks) + grid barrier + DYNAMIC tile stealing for load balance.

#define B_DIM 64
#define F_DIM 4096
#define NHOPS (B_DIM * F_DIM)          // 262144
#define NOUT (NHOPS * 64)              // 16777216
#define NQ 16384                       // strips of 16 per row
#define TPB 256
#define GRID (148 * 8)                 // all co-resident (smem ~9KB*8, regs<=32)
#define NTILES (NOUT / 4 / TPB)        // 16384

__device__ float    g_T[B_DIM * NQ];   // strip offsets (zero-shifted), aligned
__device__ float4   g_b4[NHOPS];       // per hop: (f, fold4, fold8, fold12)
__device__ unsigned g_done;
__device__ unsigned g_fin;
__device__ unsigned g_tile;            // dynamic tile counter

__device__ __forceinline__ float div_full(float a, float b) {
    float r;
    asm("div.full.f32 %0, %1, %2;" : "=f"(r) : "f"(a), "f"(b));
    return r;
}

__global__ void __launch_bounds__(TPB, 8) fused_k(const float* __restrict__ freq,
                                                  const float* __restrict__ pmod,
                                                  float* __restrict__ out) {
    __shared__ float S1[1024];
    __shared__ float R2s[1024];
    __shared__ float S2[64];
    __shared__ float I3s[64];
    __shared__ float R3s[64];
    __shared__ float R4s[4];
    __shared__ int   s_tile;

    const int tid = threadIdx.x;

    // ---------------- Phase A: rw16 tables (blocks 0..63, one row each) ------
    if (blockIdx.x < B_DIM) {
        const int row = blockIdx.x;
        const float4* fr4 = (const float4*)(freq + row * F_DIM);

        #pragma unroll
        for (int u = 0; u < 4; u++) {
            const int a = tid + u * TPB;              // strip 0..1023
            const float4 fv = __ldg(&fr4[a]);
            float s0 = 0.f, s1 = 0.f, s2 = 0.f, s3 = 0.f;
            float4 b0, b1, b2, b3;
            b0.x = fv.x; b1.x = fv.y; b2.x = fv.z; b3.x = fv.w;
            #pragma unroll
            for (int i = 0; i < 16; i++) {
                s0 = __fadd_rn(s0, fv.x);
                s1 = __fadd_rn(s1, fv.y);
                s2 = __fadd_rn(s2, fv.z);
                s3 = __fadd_rn(s3, fv.w);
                if (i == 3)  { b0.y = s0; b1.y = s1; b2.y = s2; b3.y = s3; }
                if (i == 7)  { b0.z = s0; b1.z = s1; b2.z = s2; b3.z = s3; }
                if (i == 11) { b0.w = s0; b1.w = s1; b2.w = s2; b3.w = s3; }
            }
            float4* bdst = &g_b4[row * F_DIM + 4 * a];
            bdst[0] = b0; bdst[1] = b1; bdst[2] = b2; bdst[3] = b3;
            float acc = 0.f;
            #pragma unroll
            for (int i = 0; i < 4; i++) acc = __fadd_rn(acc, s0);
            #pragma unroll
            for (int i = 0; i < 4; i++) acc = __fadd_rn(acc, s1);
            #pragma unroll
            for (int i = 0; i < 4; i++) acc = __fadd_rn(acc, s2);
            #pragma unroll
            for (int i = 0; i < 4; i++) acc = __fadd_rn(acc, s3);
            S1[a] = acc;
        }
        __syncthreads();

        if (tid < 64) {
            const float4* s1v = (const float4*)&S1[16 * tid];
            float acc = 0.f;
            #pragma unroll
            for (int i = 0; i < 4; i++) {
                float4 v = s1v[i];
                acc = __fadd_rn(acc, v.x); acc = __fadd_rn(acc, v.y);
                acc = __fadd_rn(acc, v.z); acc = __fadd_rn(acc, v.w);
            }
            S2[tid] = acc;
        }
        __syncthreads();
        if (tid < 4) {
            float acc = 0.f;
            #pragma unroll
            for (int i = 0; i < 16; i++) {
                acc = __fadd_rn(acc, S2[16 * tid + i]);
                I3s[16 * tid + i] = acc;
            }
        }
        __syncthreads();
        if (tid == 0) {
            float acc = 0.f;
            #pragma unroll
            for (int d = 0; d < 4; d++) {
                acc = __fadd_rn(acc, I3s[16 * d + 15]);
                R4s[d] = acc;
            }
        }
        __syncthreads();
        if (tid < 64)
            R3s[tid] = (tid >= 16) ? __fadd_rn(I3s[tid], R4s[(tid >> 4) - 1]) : I3s[tid];
        __syncthreads();
        if (tid < 64) {
            float acc = 0.f;
            #pragma unroll
            for (int i = 0; i < 16; i++) {
                acc = __fadd_rn(acc, S1[16 * tid + i]);
                R2s[16 * tid + i] = (tid > 0) ? __fadd_rn(acc, R3s[tid - 1]) : acc;
            }
        }
        __syncthreads();

        #pragma unroll
        for (int u = 0; u < 4; u++) {
            const int a = tid + u * TPB;
            const float4 fv = __ldg(&fr4[a]);
            float s0 = 0.f, s1 = 0.f, s2 = 0.f, s3 = 0.f;
            #pragma unroll
            for (int i = 0; i < 16; i++) {
                s0 = __fadd_rn(s0, fv.x);
                s1 = __fadd_rn(s1, fv.y);
                s2 = __fadd_rn(s2, fv.z);
                s3 = __fadd_rn(s3, fv.w);
            }
            const float off = (a > 0) ? R2s[a - 1] : 0.0f;
            float tbuf[16];
            if (a == 0) tbuf[0] = 0.0f;
            else {
                float offp = (a > 1) ? R2s[a - 2] : 0.0f;
                tbuf[0] = __fadd_rn(S1[a - 1], offp);
            }
            float acc = 0.f;
            #pragma unroll
            for (int i = 0; i < 15; i++) {
                float v = (i < 4) ? s0 : (i < 8) ? s1 : (i < 12) ? s2 : s3;
                acc = __fadd_rn(acc, v);
                tbuf[i + 1] = __fadd_rn(acc, off);
            }
            float4* tdst = (float4*)&g_T[row * NQ + 16 * a];
            tdst[0] = make_float4(tbuf[0], tbuf[1], tbuf[2], tbuf[3]);
            tdst[1] = make_float4(tbuf[4], tbuf[5], tbuf[6], tbuf[7]);
            tdst[2] = make_float4(tbuf[8], tbuf[9], tbuf[10], tbuf[11]);
            tdst[3] = make_float4(tbuf[12], tbuf[13], tbuf[14], tbuf[15]);
        }
        __threadfence();
        __syncthreads();
        if (tid == 0) atomicAdd(&g_done, 1u);
    }

    // ---------------- grid barrier ------------------------------------------
    if (tid == 0) {
        unsigned v;
        do {
            asm volatile("ld.global.acquire.gpu.u32 %0, [%1];" : "=r"(v) : "l"(&g_done));
            if (v < (unsigned)B_DIM) __nanosleep(64);
        } while (v < (unsigned)B_DIM);
    }
    __syncthreads();

    // ---------------- Phase B: oscillator, dynamic tile stealing ------------
    const float TWO_PI_F = 6.2831853071795864769f;     // 0x40C90FDB (fl32(2pi))
    const float INV_2PI  = 0.15915494309189533577f;
    const float MAGIC    = 12582912.0f;                // 1.5 * 2^23
    const float T2W      = -1.7484556000744949e-7f;    // 2pi - fl32(2pi)

    while (true) {
        if (tid == 0) s_tile = (int)atomicAdd(&g_tile, 1u);
        __syncthreads();
        const int tile = s_tile;
        __syncthreads();
        if (tile >= NTILES) break;

        const int gq  = tile * TPB + tid;
        const int hop = gq >> 4;
        const int s   = gq & 15;
        const int row = gq >> 16;

        const float4 b4 = __ldg(&g_b4[hop]);
        const float  f  = b4.x;
        const float  f0 = __ldg(freq + (row << 12));
        const float  Tv = __ldg(&g_T[row * NQ + ((gq >> 2) & (NQ - 1))]);
        const float4 p4 = __ldg((const float4*)pmod + gq);

        const int s3 = s & 3;
        float aa = (s3 & 1) ? b4.y : 0.0f;
        float bb = (s3 & 1) ? b4.w : b4.z;
        float sm = (s3 & 2) ? bb : aa;

        float pm[4] = {p4.x, p4.y, p4.z, p4.w};
        float ov[4];
        #pragma unroll
        for (int l = 0; l < 4; l++) {
            sm = __fadd_rn(sm, f);                     // I0[t] (bit-exact chain)
            float cs = __fadd_rn(sm, Tv);
            float d1 = __fadd_rn(cs, -f0);
            float d2 = __fmul_rn(d1, TWO_PI_F);
            float d3 = div_full(d2, 16000.0f);         // XLA GPU divide
            float x  = __fadd_rn(d3, pm[l]);
            // sin: mod-2pi magic reduction + single MUFU
            float t  = __fadd_rn(__fmul_rn(x, INV_2PI), MAGIC);
            float n  = __fadd_rn(t, -MAGIC);
            float r  = fmaf(-n, TWO_PI_F, x);
            r        = fmaf(-n, T2W, r);
            asm("sin.approx.f32 %0, %1;" : "=f"(ov[l]) : "f"(r));
        }
        ((float4*)out)[gq] = make_float4(ov[0], ov[1], ov[2], ov[3]);
    }

    // ---------------- replay-safe counter reset -----------------------------
    __syncthreads();
    if (tid == 0) {
        __threadfence();
        unsigned r = atomicAdd(&g_fin, 1u);
        if (r == (unsigned)(GRID - 1)) {
            atomicExch(&g_done, 0u);
            atomicExch(&g_tile, 0u);
            __threadfence();
            atomicExch(&g_fin, 0u);
        }
    }
}

extern "C" void kernel_launch(void* const* d_in, const int* in_sizes, int n_in,
                              void* d_out, int out_size) {
    const float* freq = (const float*)d_in[0];   // [64, 4096]
    const float* pmod = (const float*)d_in[1];   // [64, 262144]
    float* out = (float*)d_out;                  // [64, 262144]

    fused_k<<<GRID, TPB>>>(freq, pmod, out);
}

// round 14
// speedup vs baseline: 1.0554x; 1.0554x over previous
#include <cuda_runtime.h>
#include <cuda_bf16.h>
#include <math.h>

// Oscillator: XLA rw16 cumsum association + div.full.f32 scale chain (bit-exact
// through x); sin via mod-2pi reduction + single MUFU.SIN. Persistent kernel,
// prep (64 blocks) + grid barrier + STATIC SKEWED tile partition:
// prep blocks take 11 tiles, others 14 (64*11 + 1120*14 = 16384) to offset
// the prep blocks' late start. No in-loop atomics or barriers.

#define B_DIM 64
#define F_DIM 4096
#define NHOPS (B_DIM * F_DIM)          // 262144
#define NOUT (NHOPS * 64)              // 16777216
#define NQ 16384                       // strips of 16 per row
#define TPB 256
#define GRID (148 * 8)                 // all co-resident (smem ~9KB*8, regs<=32)
#define NTILES (NOUT / 4 / TPB)        // 16384
#define W_PREP 11
#define W_MAIN 14

__device__ float    g_T[B_DIM * NQ];   // strip offsets (zero-shifted), aligned
__device__ float4   g_b4[NHOPS];       // per hop: (f, fold4, fold8, fold12)
__device__ unsigned g_done;
__device__ unsigned g_fin;

__device__ __forceinline__ float div_full(float a, float b) {
    float r;
    asm("div.full.f32 %0, %1, %2;" : "=f"(r) : "f"(a), "f"(b));
    return r;
}

__global__ void __launch_bounds__(TPB, 8) fused_k(const float* __restrict__ freq,
                                                  const float* __restrict__ pmod,
                                                  float* __restrict__ out) {
    __shared__ float S1[1024];
    __shared__ float R2s[1024];
    __shared__ float S2[64];
    __shared__ float I3s[64];
    __shared__ float R3s[64];
    __shared__ float R4s[4];

    const int tid = threadIdx.x;
    const int bid = blockIdx.x;

    // ---------------- Phase A: rw16 tables (blocks 0..63, one row each) ------
    if (bid < B_DIM) {
        const int row = bid;
        const float4* fr4 = (const float4*)(freq + row * F_DIM);

        #pragma unroll
        for (int u = 0; u < 4; u++) {
            const int a = tid + u * TPB;              // strip 0..1023
            const float4 fv = __ldg(&fr4[a]);
            float s0 = 0.f, s1 = 0.f, s2 = 0.f, s3 = 0.f;
            float4 b0, b1, b2, b3;
            b0.x = fv.x; b1.x = fv.y; b2.x = fv.z; b3.x = fv.w;
            #pragma unroll
            for (int i = 0; i < 16; i++) {
                s0 = __fadd_rn(s0, fv.x);
                s1 = __fadd_rn(s1, fv.y);
                s2 = __fadd_rn(s2, fv.z);
                s3 = __fadd_rn(s3, fv.w);
                if (i == 3)  { b0.y = s0; b1.y = s1; b2.y = s2; b3.y = s3; }
                if (i == 7)  { b0.z = s0; b1.z = s1; b2.z = s2; b3.z = s3; }
                if (i == 11) { b0.w = s0; b1.w = s1; b2.w = s2; b3.w = s3; }
            }
            float4* bdst = &g_b4[row * F_DIM + 4 * a];
            bdst[0] = b0; bdst[1] = b1; bdst[2] = b2; bdst[3] = b3;
            float acc = 0.f;
            #pragma unroll
            for (int i = 0; i < 4; i++) acc = __fadd_rn(acc, s0);
            #pragma unroll
            for (int i = 0; i < 4; i++) acc = __fadd_rn(acc, s1);
            #pragma unroll
            for (int i = 0; i < 4; i++) acc = __fadd_rn(acc, s2);
            #pragma unroll
            for (int i = 0; i < 4; i++) acc = __fadd_rn(acc, s3);
            S1[a] = acc;
        }
        __syncthreads();

        if (tid < 64) {
            const float4* s1v = (const float4*)&S1[16 * tid];
            float acc = 0.f;
            #pragma unroll
            for (int i = 0; i < 4; i++) {
                float4 v = s1v[i];
                acc = __fadd_rn(acc, v.x); acc = __fadd_rn(acc, v.y);
                acc = __fadd_rn(acc, v.z); acc = __fadd_rn(acc, v.w);
            }
            S2[tid] = acc;
        }
        __syncthreads();
        if (tid < 4) {
            float acc = 0.f;
            #pragma unroll
            for (int i = 0; i < 16; i++) {
                acc = __fadd_rn(acc, S2[16 * tid + i]);
                I3s[16 * tid + i] = acc;
            }
        }
        __syncthreads();
        if (tid == 0) {
            float acc = 0.f;
            #pragma unroll
            for (int d = 0; d < 4; d++) {
                acc = __fadd_rn(acc, I3s[16 * d + 15]);
                R4s[d] = acc;
            }
        }
        __syncthreads();
        if (tid < 64)
            R3s[tid] = (tid >= 16) ? __fadd_rn(I3s[tid], R4s[(tid >> 4) - 1]) : I3s[tid];
        __syncthreads();
        if (tid < 64) {
            float acc = 0.f;
            #pragma unroll
            for (int i = 0; i < 16; i++) {
                acc = __fadd_rn(acc, S1[16 * tid + i]);
                R2s[16 * tid + i] = (tid > 0) ? __fadd_rn(acc, R3s[tid - 1]) : acc;
            }
        }
        __syncthreads();

        #pragma unroll
        for (int u = 0; u < 4; u++) {
            const int a = tid + u * TPB;
            const float4 fv = __ldg(&fr4[a]);
            float s0 = 0.f, s1 = 0.f, s2 = 0.f, s3 = 0.f;
            #pragma unroll
            for (int i = 0; i < 16; i++) {
                s0 = __fadd_rn(s0, fv.x);
                s1 = __fadd_rn(s1, fv.y);
                s2 = __fadd_rn(s2, fv.z);
                s3 = __fadd_rn(s3, fv.w);
            }
            const float off = (a > 0) ? R2s[a - 1] : 0.0f;
            float tbuf[16];
            if (a == 0) tbuf[0] = 0.0f;
            else {
                float offp = (a > 1) ? R2s[a - 2] : 0.0f;
                tbuf[0] = __fadd_rn(S1[a - 1], offp);
            }
            float acc = 0.f;
            #pragma unroll
            for (int i = 0; i < 15; i++) {
                float v = (i < 4) ? s0 : (i < 8) ? s1 : (i < 12) ? s2 : s3;
                acc = __fadd_rn(acc, v);
                tbuf[i + 1] = __fadd_rn(acc, off);
            }
            float4* tdst = (float4*)&g_T[row * NQ + 16 * a];
            tdst[0] = make_float4(tbuf[0], tbuf[1], tbuf[2], tbuf[3]);
            tdst[1] = make_float4(tbuf[4], tbuf[5], tbuf[6], tbuf[7]);
            tdst[2] = make_float4(tbuf[8], tbuf[9], tbuf[10], tbuf[11]);
            tdst[3] = make_float4(tbuf[12], tbuf[13], tbuf[14], tbuf[15]);
        }
        __threadfence();
        __syncthreads();
        if (tid == 0) atomicAdd(&g_done, 1u);
    }

    // ---------------- grid barrier ------------------------------------------
    if (tid == 0) {
        unsigned v;
        do {
            asm volatile("ld.global.acquire.gpu.u32 %0, [%1];" : "=r"(v) : "l"(&g_done));
            if (v < (unsigned)B_DIM) __nanosleep(64);
        } while (v < (unsigned)B_DIM);
    }
    __syncthreads();

    // ---------------- Phase B: oscillator, static skewed partition ----------
    const float TWO_PI_F = 6.2831853071795864769f;     // 0x40C90FDB (fl32(2pi))
    const float INV_2PI  = 0.15915494309189533577f;
    const float MAGIC    = 12582912.0f;                // 1.5 * 2^23
    const float T2W      = -1.7484556000744949e-7f;    // 2pi - fl32(2pi)

    int start, cnt;
    if (bid < B_DIM) { start = bid * W_PREP; cnt = W_PREP; }
    else { start = B_DIM * W_PREP + (bid - B_DIM) * W_MAIN; cnt = W_MAIN; }

    for (int tile = start; tile < start + cnt; tile++) {
        const int gq  = tile * TPB + tid;
        const int hop = gq >> 4;
        const int s   = gq & 15;
        const int row = gq >> 16;

        const float4 b4 = __ldg(&g_b4[hop]);
        const float  f  = b4.x;
        const float  f0 = __ldg(freq + (row << 12));
        const float  Tv = __ldg(&g_T[row * NQ + ((gq >> 2) & (NQ - 1))]);
        const float4 p4 = __ldg((const float4*)pmod + gq);

        const int s3 = s & 3;
        float aa = (s3 & 1) ? b4.y : 0.0f;
        float bb = (s3 & 1) ? b4.w : b4.z;
        float sm = (s3 & 2) ? bb : aa;

        float pm[4] = {p4.x, p4.y, p4.z, p4.w};
        float ov[4];
        #pragma unroll
        for (int l = 0; l < 4; l++) {
            sm = __fadd_rn(sm, f);                     // I0[t] (bit-exact chain)
            float cs = __fadd_rn(sm, Tv);
            float d1 = __fadd_rn(cs, -f0);
            float d2 = __fmul_rn(d1, TWO_PI_F);
            float d3 = div_full(d2, 16000.0f);         // XLA GPU divide
            float x  = __fadd_rn(d3, pm[l]);
            // sin: mod-2pi magic reduction + single MUFU
            float t  = __fadd_rn(__fmul_rn(x, INV_2PI), MAGIC);
            float n  = __fadd_rn(t, -MAGIC);
            float r  = fmaf(-n, TWO_PI_F, x);
            r        = fmaf(-n, T2W, r);
            asm("sin.approx.f32 %0, %1;" : "=f"(ov[l]) : "f"(r));
        }
        ((float4*)out)[gq] = make_float4(ov[0], ov[1], ov[2], ov[3]);
    }

    // ---------------- replay-safe counter reset -----------------------------
    __syncthreads();
    if (tid == 0) {
        __threadfence();
        unsigned r = atomicAdd(&g_fin, 1u);
        if (r == (unsigned)(GRID - 1)) {
            atomicExch(&g_done, 0u);
            __threadfence();
            atomicExch(&g_fin, 0u);
        }
    }
}

extern "C" void kernel_launch(void* const* d_in, const int* in_sizes, int n_in,
                              void* d_out, int out_size) {
    const float* freq = (const float*)d_in[0];   // [64, 4096]
    const float* pmod = (const float*)d_in[1];   // [64, 262144]
    float* out = (float*)d_out;                  // [64, 262144]

    fused_k<<<GRID, TPB>>>(freq, pmod, out);
}